// round 3
// baseline (speedup 1.0000x reference)
#include <cuda_runtime.h>
#include <math.h>

#define BIMG 4
#define HIMG 80
#define WIMG 80
#define HP   74            // 80 - 7 + 1 valid window positions
#define IMGPIX (HIMG*WIMG)

// 1 / (49 * sqrt(2*pi*2.5^2))
#define KDE_SCALE 3.2566726960192768e-03f
// -1 / (2 * 2.5^2)
#define NEG_INV2B2 (-0.08f)

// ---------------------------------------------------------------------------
// One block per (row-band py, image b). Fully fused:
//   1) load input rows py-2..py+8 (zero-padded) to smem
//   2) blur(5x5)/round -> sharp -> division  (integer-valued image in smem)
//   3) column-sum KDE table S(r, xp, dc): 7 exps per entry
//   4) per-window entropy from S (adds + 49 logs), deterministic reduction
//   5) write full output row py+3 (incl. zero border); bands at the ends
//      also zero the untouched border rows.
// ---------------------------------------------------------------------------
__global__ __launch_bounds__(256, 2)
void entropy_band_kernel(const float* __restrict__ x, float* __restrict__ out) {
    __shared__ float xs[11 * WIMG];          // input rows py-2 .. py+8
    __shared__ float dv[7 * WIMG];           // "division" rows py .. py+6
    __shared__ float S[7 * WIMG * 13];       // column sums, dc = xc-xp+6 in [0,12]
    __shared__ float enthalf[2 * HP];        // two half-sums per window

    const int tid = threadIdx.x;
    const int py  = blockIdx.x;              // 0..73
    const int b   = blockIdx.y;              // 0..3
    const float* img = x + b * IMGPIX;

    // -- 1: load input rows (zero pad out-of-range rows for the blur) --------
    for (int i = tid; i < 11 * WIMG; i += 256) {
        int r = i / WIMG, c = i - (i / WIMG) * WIMG;
        int row = py - 2 + r;
        xs[i] = (row >= 0 && row < HIMG) ? img[row * WIMG + c] : 0.0f;
    }
    __syncthreads();

    // -- 2: preprocessing (exact-rounding ops; division values are integers) -
    for (int i = tid; i < 7 * WIMG; i += 256) {
        int r = i / WIMG, c = i - r * WIMG;
        float sum = 0.0f;
        #pragma unroll
        for (int dy = 0; dy < 5; dy++) {
            const float* rowp = xs + (r + dy) * WIMG;
            #pragma unroll
            for (int dx = -2; dx <= 2; dx++) {
                int cc = c + dx;
                if (cc >= 0 && cc < WIMG) sum = __fadd_rn(sum, rowp[cc]);
            }
        }
        float smooth = rintf(__fdiv_rn(sum, 25.0f));
        float cv     = xs[(r + 2) * WIMG + c];
        float sharp  = rintf(fminf(fmaxf(
                          __fsub_rn(__fmul_rn(2.5f, cv), __fmul_rn(1.25f, smooth)),
                          0.0f), 255.0f));
        float divi   = rintf(fminf(fmaxf(
                          __fdiv_rn(__fmul_rn(sharp, 255.0f),
                                    __fadd_rn(smooth, 1e-8f)),
                          0.0f), 255.0f));
        dv[i] = divi;
    }
    __syncthreads();

    // -- 3: column-sum KDE table --------------------------------------------
    // S[r][xp][dc] = sum_{r2} exp(-(v[r][xp] - v[r2][xp-6+dc])^2 / 12.5)
    for (int q = tid; q < 7 * WIMG * 13; q += 256) {
        int dc = q % 13;
        int t2 = q / 13;
        int xp = t2 % WIMG;
        int r  = t2 / WIMG;
        int xc = xp - 6 + dc;
        float s = 0.0f;
        if (xc >= 0 && xc < WIMG) {
            float vi = dv[r * WIMG + xp];
            #pragma unroll
            for (int r2 = 0; r2 < 7; r2++) {
                float d = vi - dv[r2 * WIMG + xc];
                s += __expf(d * d * NEG_INV2B2);
            }
        }
        S[q] = s;
    }
    __syncthreads();

    // -- 4: per-window entropy (2 threads per window; deterministic) ---------
    if (tid < 2 * HP) {
        int xwin = tid >> 1;
        int half = tid & 1;
        int i0 = half ? 25 : 0;
        int i1 = half ? 49 : 25;
        float acc = 0.0f;
        for (int i = i0; i < i1; i++) {
            int r = i / 7, c = i - r * 7;
            // p(r,c) = sum over the 7 window columns: dc = c2 - c + 6
            const float* Sp = S + (r * WIMG + (xwin + c)) * 13 + (6 - c);
            float p = 0.0f;
            #pragma unroll
            for (int c2 = 0; c2 < 7; c2++) p += Sp[c2];
            acc += __logf(__fmul_rn(p, KDE_SCALE) + 1e-8f);
        }
        enthalf[half * HP + xwin] = acc;
    }
    __syncthreads();

    // -- 5: write output row py+3 (full row, zero border); end bands zero the
    //       three untouched border rows at top/bottom.
    if (tid < WIMG) {
        float v = 0.0f;
        if (tid >= 3 && tid < 3 + HP) {
            int xwin = tid - 3;
            v = -__fdiv_rn(enthalf[xwin] + enthalf[HP + xwin], 49.0f);
        }
        float* obase = out + b * IMGPIX;
        obase[(py + 3) * WIMG + tid] = v;
        if (py < 3)   obase[py * WIMG + tid] = 0.0f;        // rows 0,1,2
        if (py >= 71) obase[(py + 6) * WIMG + tid] = 0.0f;  // rows 77,78,79
    }
}

// ---------------------------------------------------------------------------
extern "C" void kernel_launch(void* const* d_in, const int* in_sizes, int n_in,
                              void* d_out, int out_size) {
    const float* x = (const float*)d_in[0];
    float* out     = (float*)d_out;
    dim3 grid(HP, BIMG);                 // 74 x 4 = 296 blocks
    entropy_band_kernel<<<grid, 256>>>(x, out);
}

// round 4
// speedup vs baseline: 1.5364x; 1.5364x over previous
#include <cuda_runtime.h>
#include <math.h>

#define BIMG 4
#define HIMG 80
#define WIMG 80
#define HP   74               // valid window positions per axis
#define IMGPIX (HIMG*WIMG)
#define BT   576              // threads per block (18 warps)

// 1 / (49 * sqrt(2*pi*2.5^2))
#define KDE_SCALE 3.2566726960192768e-03f
// -1/(2*2.5^2) * log2(e)  (fold exp -> exp2)
#define NEG_C2    (-0.11541560327111708f)

// dynamic smem layout (floats): xs[880] | dv[560] | S[7280] | Ltab[3920]
#define SMEM_BYTES ((880 + 560 + 7280 + 3920) * 4)

__device__ __forceinline__ float ex2f(float x) {
    float y;
    asm("ex2.approx.f32 %0, %1;" : "=f"(y) : "f"(x));
    return y;
}

// ---------------------------------------------------------------------------
// One block per (row-band py, image b). Phases:
//  1) load input rows py-2..py+8 (zero-padded)
//  2) blur/round -> sharp -> division (integer-valued floats)
//  3) symmetric column-sum KDE table S[r][xp][dc], dc = xc-xp+6 in [0,12]:
//     thread (xp, dc<=6) computes 49 exps once, writes S and its mirror.
//  4) prefix-sum over dc -> 7 window sums per (r,xp) -> log -> Ltab
//  5) entropy per window = sum of 49 Ltab entries; write output + borders
// ---------------------------------------------------------------------------
__global__ __launch_bounds__(BT, 2)
void entropy_band_kernel(const float* __restrict__ x, float* __restrict__ out) {
    extern __shared__ float sm[];
    float* xs   = sm;                 // 11*80
    float* dv   = sm + 880;           // 7*80
    float* S    = sm + 880 + 560;     // 7*80*13
    float* Ltab = S + 7280;           // 49*80  : Ltab[(r*7+c)*80 + xp]

    const int tid = threadIdx.x;
    const int py  = blockIdx.x;       // 0..73
    const int b   = blockIdx.y;       // 0..3
    const float* img = x + b * IMGPIX;

    // -- 1: zero S (entries with out-of-range columns stay 0) + load rows ----
    for (int i = tid; i < 7280; i += BT) S[i] = 0.0f;
    for (int i = tid; i < 880; i += BT) {
        int r = i / 80, c = i - (i / 80) * 80;
        int row = py - 2 + r;
        xs[i] = (row >= 0 && row < HIMG) ? img[row * 80 + c] : 0.0f;
    }
    __syncthreads();

    // -- 2: preprocessing (exact-rounding ops so rintf ties match jax) -------
    if (tid < 560) {
        int r = tid / 80, c = tid - r * 80;
        float sum = 0.0f;
        #pragma unroll
        for (int dy = 0; dy < 5; dy++) {
            const float* rowp = xs + (r + dy) * 80;
            #pragma unroll
            for (int dx = -2; dx <= 2; dx++) {
                int cc = c + dx;
                if (cc >= 0 && cc < 80) sum = __fadd_rn(sum, rowp[cc]);
            }
        }
        float smooth = rintf(__fdiv_rn(sum, 25.0f));
        float cv     = xs[(r + 2) * 80 + c];
        float sharp  = rintf(fminf(fmaxf(
                          __fsub_rn(__fmul_rn(2.5f, cv), __fmul_rn(1.25f, smooth)),
                          0.0f), 255.0f));
        float divi   = rintf(fminf(fmaxf(
                          __fdiv_rn(__fmul_rn(sharp, 255.0f),
                                    __fadd_rn(smooth, 1e-8f)),
                          0.0f), 255.0f));
        dv[tid] = divi;
    }
    __syncthreads();

    // -- 3: symmetric KDE column sums ----------------------------------------
    // S[r][xp][dc] = sum_{r2} exp(-(dv[r][xp]-dv[r2][xc])^2/12.5), xc=xp-6+dc
    if (tid < 560) {
        int dc = tid / 80;                 // 0..6
        int xp = tid - dc * 80;            // 0..79
        int xc = xp - 6 + dc;              // <= xp
        if (xc >= 0) {
            float vA[7];
            #pragma unroll
            for (int r = 0; r < 7; r++) vA[r] = dv[r * 80 + xp];
            float s[7], t[7];
            #pragma unroll
            for (int r = 0; r < 7; r++) { s[r] = 0.0f; t[r] = 0.0f; }
            #pragma unroll
            for (int r2 = 0; r2 < 7; r2++) {
                float vb = dv[r2 * 80 + xc];
                #pragma unroll
                for (int r = 0; r < 7; r++) {
                    float d = vA[r] - vb;
                    float e = ex2f(d * d * NEG_C2);
                    s[r]  += e;
                    t[r2] += e;
                }
            }
            #pragma unroll
            for (int r = 0; r < 7; r++) S[(r * 80 + xp) * 13 + dc] = s[r];
            if (dc < 6) {                  // mirror entry (dc'=12-dc at col xc)
                #pragma unroll
                for (int r = 0; r < 7; r++) S[(r * 80 + xc) * 13 + (12 - dc)] = t[r];
            }
        }
    }
    __syncthreads();

    // -- 4: window sums via prefix, then log ---------------------------------
    if (tid < 560) {                       // tid = r*80 + xp
        const float* Sp = S + tid * 13;
        float pref[14];
        pref[0] = 0.0f;
        #pragma unroll
        for (int k = 0; k < 13; k++) pref[k + 1] = pref[k] + Sp[k];
        int r = tid / 80, xp = tid - (tid / 80) * 80;
        #pragma unroll
        for (int c = 0; c < 7; c++) {
            float W = pref[13 - c] - pref[6 - c];   // >= 1 for valid windows
            Ltab[(r * 7 + c) * 80 + xp] =
                __logf(__fmul_rn(W, KDE_SCALE) + 1e-8f);
        }
    }
    __syncthreads();

    // -- 5: entropy per window + borders -------------------------------------
    float* ob = out + b * IMGPIX;
    if (tid < HP) {
        float acc = 0.0f;
        #pragma unroll
        for (int r = 0; r < 7; r++)
            #pragma unroll
            for (int c = 0; c < 7; c++)
                acc += Ltab[(r * 7 + c) * 80 + tid + c];
        ob[(py + 3) * 80 + (tid + 3)] = -__fdiv_rn(acc, 49.0f);
    }
    if (tid < 6) {                         // cols 0,1,2 and 77,78,79 of this row
        int col = (tid < 3) ? tid : (74 + tid);
        ob[(py + 3) * 80 + col] = 0.0f;
    }
    if (py < 3  && tid < 80) ob[py * 80 + tid] = 0.0f;        // rows 0..2
    if (py >= 71 && tid < 80) ob[(py + 6) * 80 + tid] = 0.0f; // rows 77..79
}

// ---------------------------------------------------------------------------
extern "C" void kernel_launch(void* const* d_in, const int* in_sizes, int n_in,
                              void* d_out, int out_size) {
    const float* x = (const float*)d_in[0];
    float* out     = (float*)d_out;

    cudaFuncSetAttribute(entropy_band_kernel,
                         cudaFuncAttributeMaxDynamicSharedMemorySize, SMEM_BYTES);
    dim3 grid(HP, BIMG);                   // 74 x 4 = 296 blocks = 1 full wave
    entropy_band_kernel<<<grid, BT, SMEM_BYTES>>>(x, out);
}